// round 5
// baseline (speedup 1.0000x reference)
#include <cuda_runtime.h>
#include <cuda_bf16.h>

#define BB   1024
#define NN   50
#define DIN  128
#define DH   256
#define G4   1024
#define DW   64

// ---------------- persistent device state (static, no runtime alloc) ----------------
__device__ float g_h[2][BB * DH];
__device__ float g_c[BB * DH];
__device__ float g_blend1[BB * NN * DW];   // [row=b*50+n][64]
__device__ float g_Wf[DW * DIN];           // fused W1@W_enc
__device__ float g_bf[DW];                 // fused W1@b_enc
__device__ float g_bias[G4];               // b_ih + b_hh
__device__ float g_W2t[DH * DW];           // W2 transposed [h][w]
__device__ int   g_xrow[BB];               // selected row index into targets (b*50+sel), -1 = zeros
__device__ unsigned long long g_sel[BB];   // selected bitmask (N=50 <= 64)

typedef unsigned long long u64;

// ---- packed f32x2 helpers (FFMA2 path: 2x fp32 throughput on sm_103a) ----
__device__ __forceinline__ u64 pk2(float x) {
    u64 r; unsigned u = __float_as_uint(x);
    asm("mov.b64 %0, {%1, %1};" : "=l"(r) : "r"(u));
    return r;
}
__device__ __forceinline__ float2 upk2(u64 v) {
    float2 f; asm("mov.b64 {%0, %1}, %2;" : "=f"(f.x), "=f"(f.y) : "l"(v));
    return f;
}
__device__ __forceinline__ void fma2(u64& d, u64 a, u64 b) {
    asm("fma.rn.f32x2 %0, %1, %2, %0;" : "+l"(d) : "l"(a), "l"(b));
}

// Accurate-regardless-of-fastmath tanh (expf-based)
__device__ __forceinline__ float tanh_acc(float x) {
    return 1.0f - 2.0f / (expf(2.0f * x) + 1.0f);
}
__device__ __forceinline__ float sigm(float x) {
    return 1.0f / (1.0f + expf(-x));
}

// ---------------- init ----------------
__global__ void init_kernel(const float* __restrict__ h0, const float* __restrict__ c0,
                            const float* __restrict__ b_ih, const float* __restrict__ b_hh,
                            const float* __restrict__ W2) {
    int i = blockIdx.x * blockDim.x + threadIdx.x;
    g_h[0][i] = h0[i];
    g_c[i]    = c0[i];
    if (i < DH * DW) {
        int h = i >> 6, w = i & 63;
        g_W2t[i] = W2[w * DH + h];
    }
    if (i < G4) g_bias[i] = b_ih[i] + b_hh[i];
    if (i < BB) { g_xrow[i] = -1; g_sel[i] = 0ull; }
}

// ---------------- fused encoder weight: Wf = W1 @ W_enc, bf = W1 @ b_enc ----------------
__global__ void wf_kernel(const float* __restrict__ W1, const float* __restrict__ Wenc,
                          const float* __restrict__ benc) {
    int w = blockIdx.x;
    int i = threadIdx.x;
    const float* w1 = W1 + w * DH;
    float s = 0.f;
    for (int h = 0; h < DH; h++) s += w1[h] * Wenc[h * DIN + i];
    g_Wf[w * DIN + i] = s;
    __shared__ float red[128];
    float p = 0.f;
    for (int h = i; h < DH; h += 128) p += w1[h] * benc[h];
    red[i] = p;
    __syncthreads();
    for (int o = 64; o; o >>= 1) { if (i < o) red[i] += red[i + o]; __syncthreads(); }
    if (i == 0) g_bf[w] = red[0];
}

// ---------------- blend1 = targets @ Wf^T + bf ----------------
__global__ __launch_bounds__(128) void blend1_kernel(const float* __restrict__ targets) {
    __shared__ __align__(16) float As[32][68];
    __shared__ __align__(16) float Bs[32][68];
    int t   = threadIdx.x;
    int rb0 = blockIdx.x * 64;
    int c0  = (t & 7) * 8;
    int r0  = (t >> 3) * 4;
    u64 acc2[4][4];
    #pragma unroll
    for (int i = 0; i < 4; i++)
        #pragma unroll
        for (int p = 0; p < 4; p++) acc2[i][p] = 0ull;

    float4 pa[4], pb[4];
    #pragma unroll
    for (int i = 0; i < 4; i++) {
        int f4 = i * 128 + t; int row = f4 >> 3, kq = f4 & 7;
        pa[i] = *(const float4*)(targets + (size_t)(rb0 + row) * DIN + kq * 4);
        pb[i] = *(const float4*)(g_Wf + (size_t)row * DIN + kq * 4);
    }
    #pragma unroll 1
    for (int kt = 0; kt < 4; kt++) {
        __syncthreads();
        #pragma unroll
        for (int i = 0; i < 4; i++) {
            int f4 = i * 128 + t; int row = f4 >> 3, kq = f4 & 7;
            As[kq * 4 + 0][row] = pa[i].x; As[kq * 4 + 1][row] = pa[i].y;
            As[kq * 4 + 2][row] = pa[i].z; As[kq * 4 + 3][row] = pa[i].w;
            Bs[kq * 4 + 0][row] = pb[i].x; Bs[kq * 4 + 1][row] = pb[i].y;
            Bs[kq * 4 + 2][row] = pb[i].z; Bs[kq * 4 + 3][row] = pb[i].w;
        }
        __syncthreads();
        if (kt < 3) {
            int k0 = (kt + 1) * 32;
            #pragma unroll
            for (int i = 0; i < 4; i++) {
                int f4 = i * 128 + t; int row = f4 >> 3, kq = f4 & 7;
                pa[i] = *(const float4*)(targets + (size_t)(rb0 + row) * DIN + k0 + kq * 4);
                pb[i] = *(const float4*)(g_Wf + (size_t)row * DIN + k0 + kq * 4);
            }
        }
        #pragma unroll
        for (int kk = 0; kk < 32; kk++) {
            float4 av = *reinterpret_cast<const float4*>(&As[kk][r0]);
            ulonglong2 u0 = *reinterpret_cast<const ulonglong2*>(&Bs[kk][c0]);
            ulonglong2 u1 = *reinterpret_cast<const ulonglong2*>(&Bs[kk][c0 + 4]);
            u64 aa;
            aa = pk2(av.x); fma2(acc2[0][0], aa, u0.x); fma2(acc2[0][1], aa, u0.y);
                            fma2(acc2[0][2], aa, u1.x); fma2(acc2[0][3], aa, u1.y);
            aa = pk2(av.y); fma2(acc2[1][0], aa, u0.x); fma2(acc2[1][1], aa, u0.y);
                            fma2(acc2[1][2], aa, u1.x); fma2(acc2[1][3], aa, u1.y);
            aa = pk2(av.z); fma2(acc2[2][0], aa, u0.x); fma2(acc2[2][1], aa, u0.y);
                            fma2(acc2[2][2], aa, u1.x); fma2(acc2[2][3], aa, u1.y);
            aa = pk2(av.w); fma2(acc2[3][0], aa, u0.x); fma2(acc2[3][1], aa, u0.y);
                            fma2(acc2[3][2], aa, u1.x); fma2(acc2[3][3], aa, u1.y);
        }
    }
    #pragma unroll
    for (int i = 0; i < 4; i++) {
        size_t row = (size_t)(rb0 + r0 + i);
        float2 f0 = upk2(acc2[i][0]), f1 = upk2(acc2[i][1]);
        float2 f2 = upk2(acc2[i][2]), f3 = upk2(acc2[i][3]);
        float4 o0, o1;
        o0.x = f0.x + g_bf[c0 + 0]; o0.y = f0.y + g_bf[c0 + 1];
        o0.z = f1.x + g_bf[c0 + 2]; o0.w = f1.y + g_bf[c0 + 3];
        o1.x = f2.x + g_bf[c0 + 4]; o1.y = f2.y + g_bf[c0 + 5];
        o1.z = f3.x + g_bf[c0 + 6]; o1.w = f3.y + g_bf[c0 + 7];
        *(float4*)(g_blend1 + row * DW + c0)     = o0;
        *(float4*)(g_blend1 + row * DW + c0 + 4) = o1;
    }
}

// ---------------- per-step fused GEMM + LSTM cell (FFMA2 + Bs chunk swizzle) ----------------
// Bs physical column: chunk(c>>2) -> chunk ^ ((chunk>>3)&7), within-chunk order kept.
__global__ __launch_bounds__(256) void gates_kernel(const float* __restrict__ targets,
                                                    const float* __restrict__ W_ih,
                                                    const float* __restrict__ W_hh,
                                                    int par) {
    __shared__ __align__(16) float As[32][68];
    __shared__ __align__(16) float Bs[32][132];
    __shared__ int sxr[64];
    const float* h_in  = g_h[par];
    float*       h_out = g_h[par ^ 1];
    int t   = threadIdx.x;
    int bm0 = blockIdx.x * 64;
    int jh0 = blockIdx.y * 32;
    if (t < 64) sxr[t] = g_xrow[bm0 + t];
    __syncthreads();
    int c0 = (t & 15) * 8;
    int r0 = (t >> 4) * 4;
    // swizzled load offsets for this thread's two 4-float chunks (kk-invariant)
    int i0 = c0 >> 2;
    int s0 = ((i0 ^ ((i0 >> 3) & 7)) << 2);
    int s1 = (((i0 + 1) ^ (((i0 + 1) >> 3) & 7)) << 2);
    // store-side precompute
    int scol[4], srow4[4], sJ[4];
    #pragma unroll
    for (int i = 0; i < 4; i++) {
        int f4 = i * 256 + t; int c = f4 >> 3; int kq = f4 & 7;
        int ch = c >> 2;
        scol[i]  = ((ch ^ ((ch >> 3) & 7)) << 2) | (c & 3);
        srow4[i] = kq * 4;
        sJ[i]    = (c & 3) * DH + jh0 + (c >> 2);
    }
    int arow[2], akq4[2];
    #pragma unroll
    for (int i = 0; i < 2; i++) { int f4 = i * 256 + t; arow[i] = f4 >> 3; akq4[i] = (f4 & 7) * 4; }

    u64 acc2[4][4];
    #pragma unroll
    for (int i = 0; i < 4; i++)
        #pragma unroll
        for (int p = 0; p < 4; p++) acc2[i][p] = 0ull;

    float4 pa[2], pb[4];
    #pragma unroll
    for (int i = 0; i < 2; i++) {
        int xr = sxr[arow[i]];
        pa[i] = (xr >= 0) ? *(const float4*)(targets + (size_t)xr * DIN + akq4[i])
                          : make_float4(0.f, 0.f, 0.f, 0.f);
    }
    #pragma unroll
    for (int i = 0; i < 4; i++)
        pb[i] = *(const float4*)(W_ih + (size_t)sJ[i] * DIN + srow4[i]);

    #pragma unroll 1
    for (int kt = 0; kt < 12; kt++) {
        __syncthreads();
        #pragma unroll
        for (int i = 0; i < 2; i++) {
            As[akq4[i] + 0][arow[i]] = pa[i].x; As[akq4[i] + 1][arow[i]] = pa[i].y;
            As[akq4[i] + 2][arow[i]] = pa[i].z; As[akq4[i] + 3][arow[i]] = pa[i].w;
        }
        #pragma unroll
        for (int i = 0; i < 4; i++) {
            Bs[srow4[i] + 0][scol[i]] = pb[i].x; Bs[srow4[i] + 1][scol[i]] = pb[i].y;
            Bs[srow4[i] + 2][scol[i]] = pb[i].z; Bs[srow4[i] + 3][scol[i]] = pb[i].w;
        }
        __syncthreads();
        if (kt < 11) {
            int k0 = (kt + 1) * 32;
            #pragma unroll
            for (int i = 0; i < 2; i++) {
                int k = k0 + akq4[i];
                float4 v;
                if (k < DIN) {
                    int xr = sxr[arow[i]];
                    v = (xr >= 0) ? *(const float4*)(targets + (size_t)xr * DIN + k)
                                  : make_float4(0.f, 0.f, 0.f, 0.f);
                } else {
                    v = *(const float4*)(h_in + (size_t)(bm0 + arow[i]) * DH + (k - DIN));
                }
                pa[i] = v;
            }
            #pragma unroll
            for (int i = 0; i < 4; i++) {
                int k = k0 + srow4[i];
                pb[i] = (k < DIN) ? *(const float4*)(W_ih + (size_t)sJ[i] * DIN + k)
                                  : *(const float4*)(W_hh + (size_t)sJ[i] * DH + (k - DIN));
            }
        }
        #pragma unroll
        for (int kk = 0; kk < 32; kk++) {
            float4 av = *reinterpret_cast<const float4*>(&As[kk][r0]);
            ulonglong2 u0 = *reinterpret_cast<const ulonglong2*>(&Bs[kk][s0]);
            ulonglong2 u1 = *reinterpret_cast<const ulonglong2*>(&Bs[kk][s1]);
            u64 aa;
            aa = pk2(av.x); fma2(acc2[0][0], aa, u0.x); fma2(acc2[0][1], aa, u0.y);
                            fma2(acc2[0][2], aa, u1.x); fma2(acc2[0][3], aa, u1.y);
            aa = pk2(av.y); fma2(acc2[1][0], aa, u0.x); fma2(acc2[1][1], aa, u0.y);
                            fma2(acc2[1][2], aa, u1.x); fma2(acc2[1][3], aa, u1.y);
            aa = pk2(av.z); fma2(acc2[2][0], aa, u0.x); fma2(acc2[2][1], aa, u0.y);
                            fma2(acc2[2][2], aa, u1.x); fma2(acc2[2][3], aa, u1.y);
            aa = pk2(av.w); fma2(acc2[3][0], aa, u0.x); fma2(acc2[3][1], aa, u0.y);
                            fma2(acc2[3][2], aa, u1.x); fma2(acc2[3][3], aa, u1.y);
        }
    }

    // LSTM epilogue: pairs (i,f) and (g,o) per quadruple
    int jjb = c0 >> 2;
    #pragma unroll
    for (int i = 0; i < 4; i++) {
        size_t row = (size_t)(bm0 + r0 + i);
        #pragma unroll
        for (int q = 0; q < 2; q++) {
            int hidx = jh0 + jjb + q;
            float2 p0 = upk2(acc2[i][2 * q]);
            float2 p1 = upk2(acc2[i][2 * q + 1]);
            float ig = p0.x + g_bias[hidx];
            float fg = p0.y + g_bias[DH + hidx];
            float gg = p1.x + g_bias[2 * DH + hidx];
            float og = p1.y + g_bias[3 * DH + hidx];
            float cold = g_c[row * DH + hidx];
            float cn = sigm(fg) * cold + sigm(ig) * tanh_acc(gg);
            g_c[row * DH + hidx]   = cn;
            h_out[row * DH + hidx] = sigm(og) * tanh_acc(cn);
        }
    }
}

// ---------------- per-step attention: 8 batch rows per block (amortize W2t) ----------------
__global__ __launch_bounds__(256) void attn_kernel(const float* __restrict__ vt,
                                                   float* __restrict__ out,
                                                   int step, int hpar) {
    int t  = threadIdx.x;
    int b0 = blockIdx.x * 8;
    const float* h_in = g_h[hpar];
    __shared__ float sh_h[8][DH];
    __shared__ float sh_b2[8][DW];
    __shared__ float sh_vt[DW];
    __shared__ float sh_out[8][52];

    #pragma unroll
    for (int i = 0; i < 8; i++)
        sh_h[i][t] = h_in[(size_t)(b0 + i) * DH + t];
    if (t < DW) sh_vt[t] = vt[t];
    __syncthreads();

    // blend2 = h @ W2^T; thread handles (w, rows rr and rr+4); W2t reads coalesced, L1/L2 hot
    {
        int w = t & 63, rr = t >> 6;
        const float* w2c = g_W2t + w;
        float a0 = 0.f, a1 = 0.f, bb0 = 0.f, bb1 = 0.f;
        #pragma unroll 8
        for (int hh = 0; hh < DH; hh += 2) {
            float w0 = w2c[(size_t)hh * DW];
            float w1 = w2c[(size_t)(hh + 1) * DW];
            a0  += sh_h[rr][hh]     * w0;  a1  += sh_h[rr][hh + 1]     * w1;
            bb0 += sh_h[rr + 4][hh] * w0;  bb1 += sh_h[rr + 4][hh + 1] * w1;
        }
        sh_b2[rr][w]     = a0 + a1;
        sh_b2[rr + 4][w] = bb0 + bb1;
    }
    __syncthreads();

    // one warp per batch row: scores, argmax, softmax
    int wid = t >> 5, lane = t & 31;
    int b = b0 + wid;
    unsigned long long selb = g_sel[b];
    const float* b1 = g_blend1 + (size_t)b * NN * DW;
    float bl2a = sh_b2[wid][lane],  bl2b = sh_b2[wid][32 + lane];
    float vta  = sh_vt[lane],       vtb  = sh_vt[32 + lane];

    #pragma unroll 2
    for (int n = 0; n < NN; n++) {
        float v = tanh_acc(b1[n * DW + lane]      + bl2a) * vta
                + tanh_acc(b1[n * DW + 32 + lane] + bl2b) * vtb;
        #pragma unroll
        for (int o = 16; o; o >>= 1) v += __shfl_xor_sync(0xffffffffu, v, o);
        if (lane == 0) sh_out[wid][n] = ((selb >> n) & 1ull) ? -1.0e9f : v;
    }
    __syncwarp();

    float v1 = sh_out[wid][lane];
    float v2 = (lane + 32 < NN) ? sh_out[wid][lane + 32] : -3.4e38f;
    float bv; int bi;
    if (v2 > v1) { bv = v2; bi = lane + 32; } else { bv = v1; bi = lane; }
    #pragma unroll
    for (int o = 16; o; o >>= 1) {
        float ov = __shfl_xor_sync(0xffffffffu, bv, o);
        int   oi = __shfl_xor_sync(0xffffffffu, bi, o);
        if (ov > bv || (ov == bv && oi < bi)) { bv = ov; bi = oi; }
    }

    float e1 = expf(v1 - bv);
    float e2 = (lane + 32 < NN) ? expf(v2 - bv) : 0.f;
    float s = e1 + e2;
    #pragma unroll
    for (int o = 16; o; o >>= 1) s += __shfl_xor_sync(0xffffffffu, s, o);

    float* op = out + (size_t)b * NN * NN + (size_t)step * NN;
    op[lane] = fmaxf(e1 / s, 1e-9f);
    if (lane + 32 < NN) op[lane + 32] = fmaxf(e2 / s, 1e-9f);

    if (lane == 0) {
        g_sel[b]  = selb | (1ull << bi);
        g_xrow[b] = b * NN + bi;
    }
}

// ---------------- launch ----------------
extern "C" void kernel_launch(void* const* d_in, const int* in_sizes, int n_in,
                              void* d_out, int out_size) {
    const float* targets = (const float*)d_in[0];
    const float* h0      = (const float*)d_in[1];
    const float* c0      = (const float*)d_in[2];
    const float* W_enc   = (const float*)d_in[3];
    const float* b_enc   = (const float*)d_in[4];
    const float* W_ih    = (const float*)d_in[5];
    const float* W_hh    = (const float*)d_in[6];
    const float* b_ih    = (const float*)d_in[7];
    const float* b_hh    = (const float*)d_in[8];
    const float* W1      = (const float*)d_in[9];
    const float* W2      = (const float*)d_in[10];
    const float* vt      = (const float*)d_in[11];
    float* out = (float*)d_out;

    init_kernel<<<1024, 256>>>(h0, c0, b_ih, b_hh, W2);
    wf_kernel<<<64, 128>>>(W1, W_enc, b_enc);
    blend1_kernel<<<BB * NN / 64, 128>>>(targets);

    for (int s = 0; s < NN; s++) {
        int par = s & 1;
        gates_kernel<<<dim3(16, 8), 256>>>(targets, W_ih, W_hh, par);
        attn_kernel<<<128, 256>>>(vt, out, s, par ^ 1);
    }
}